// round 6
// baseline (speedup 1.0000x reference)
#include <cuda_runtime.h>

// Problem: B=8, L=256, Z=16, H=256
// Reassociated contraction order (12.9 GFLOP total):
//   A: Wc[bz][i][j] = sum_o cls[bz][o] * W[i][o][j]         (per i: GEMM 128x256x256)
//   B: t[b][x][z][j] = sum_i start[b][x][i] * Wc[bz][i][j]  (per bz: GEMM 256x256x256 NN)
//   C: out[b][x][y][z] = sum_j t[b][x][z][j] * end[b][y][j] (per b:  GEMM 4096x256x256 NT)
// FFMA2 inner loop, column-paired accumulators, A stored DUPLICATED in smem
// (zero per-iteration dup movs), global double-buffering.

__device__ float g_wc[8388608];   // [bz=128][i=256][j=256]
__device__ float g_t [8388608];   // [b=8][x=256][z=16][j=256]

#define TILE 128
#define KT   8
#define NSTAGE 32                 // 256 / KT

typedef unsigned long long u64;

__device__ __forceinline__ u64 dupf(float v) {
    u64 r; unsigned u = __float_as_uint(v);
    asm("mov.b64 %0, {%1, %1};" : "=l"(r) : "r"(u));
    return r;
}
__device__ __forceinline__ void fma2(u64& d, u64 a, u64 b) {
    asm("fma.rn.f32x2 %0, %1, %2, %0;" : "+l"(d) : "l"(a), "l"(b));
}
__device__ __forceinline__ void unpk(u64 v, float& lo, float& hi) {
    unsigned l, h;
    asm("mov.b64 {%0, %1}, %2;" : "=r"(l), "=r"(h) : "l"(v));
    lo = __uint_as_float(l); hi = __uint_as_float(h);
}

// As_dup: [KT][256] — each of 128 row-values stored twice at [row*2], [row*2+1].
// Bs:     [KT][128] — plain.
// acc[i][jp] = rows ty*8+i, col-pair (tx*8+2jp, tx*8+2jp+1).
__device__ __forceinline__ void mk_compute(const float (*Asd)[2 * TILE],
                                           const float (*Bs)[TILE],
                                           int tx, int ty, u64 acc[8][4])
{
#pragma unroll
    for (int kk = 0; kk < KT; kk++) {
        ulonglong2 t0 = *(const ulonglong2*)&Asd[kk][ty * 16 + 0];
        ulonglong2 t1 = *(const ulonglong2*)&Asd[kk][ty * 16 + 4];
        ulonglong2 t2 = *(const ulonglong2*)&Asd[kk][ty * 16 + 8];
        ulonglong2 t3 = *(const ulonglong2*)&Asd[kk][ty * 16 + 12];
        u64 ad[8];
        ad[0] = t0.x; ad[1] = t0.y; ad[2] = t1.x; ad[3] = t1.y;
        ad[4] = t2.x; ad[5] = t2.y; ad[6] = t3.x; ad[7] = t3.y;

        ulonglong2 b01 = *(const ulonglong2*)&Bs[kk][tx * 8];
        ulonglong2 b23 = *(const ulonglong2*)&Bs[kk][tx * 8 + 4];
        u64 bp[4]; bp[0] = b01.x; bp[1] = b01.y; bp[2] = b23.x; bp[3] = b23.y;

#pragma unroll
        for (int i = 0; i < 8; i++)
#pragma unroll
            for (int jp = 0; jp < 4; jp++)
                fma2(acc[i][jp], ad[i], bp[jp]);
    }
}

__device__ __forceinline__ void mk_unpack(u64 acc[8][4], float c[8][8])
{
#pragma unroll
    for (int i = 0; i < 8; i++)
#pragma unroll
        for (int jp = 0; jp < 4; jp++)
            unpk(acc[i][jp], c[i][2 * jp], c[i][2 * jp + 1]);
}

// store one fp32 duplicated into As_dup[r][lr*2..lr*2+1]
__device__ __forceinline__ void sts_dup(float* p, float v) {
    *(u64*)p = dupf(v);
}

// ---------------------------------------------------------------------------
// Kernel A: per i (blockIdx.z), C[bz][j] = cls[bz][:] @ W[i][:][:]
// ---------------------------------------------------------------------------
__global__ __launch_bounds__(256, 2)
void kernA(const float* __restrict__ cls, const float* __restrict__ W)
{
    int i_dim = blockIdx.z;
    const float* A  = cls;                        // [128][256]
    const float* Bm = W + (long)i_dim * 65536;    // [o=256][j=256]

    __shared__ float As[2][KT][2 * TILE];
    __shared__ float Bs[2][KT][TILE];

    int tid = threadIdx.x;
    int tx = tid & 15, ty = tid >> 4;
    int n0 = blockIdx.x * TILE;

    int lr = tid >> 1;          // 0..127
    int lc = (tid & 1) * 4;     // 0 or 4
    int bk = tid >> 5;          // 0..7
    int bn = (tid & 31) * 4;    // 0..124

    u64 acc[8][4];
#pragma unroll
    for (int i = 0; i < 8; i++)
#pragma unroll
        for (int jp = 0; jp < 4; jp++) acc[i][jp] = 0ULL;

    {
        float4 av = *(const float4*)(A + (long)lr * 256 + lc);
        sts_dup(&As[0][lc + 0][lr * 2], av.x);
        sts_dup(&As[0][lc + 1][lr * 2], av.y);
        sts_dup(&As[0][lc + 2][lr * 2], av.z);
        sts_dup(&As[0][lc + 3][lr * 2], av.w);
        *(float4*)&Bs[0][bk][bn] = *(const float4*)(Bm + (long)bk * 256 + n0 + bn);
    }
    __syncthreads();

    int buf = 0;
#pragma unroll 2
    for (int s = 0; s < NSTAGE; s++) {
        float4 nav, nbv;
        if (s + 1 < NSTAGE) {
            int k1 = (s + 1) * KT;
            nav = *(const float4*)(A + (long)lr * 256 + k1 + lc);
            nbv = *(const float4*)(Bm + (long)(k1 + bk) * 256 + n0 + bn);
        }
        mk_compute(As[buf], Bs[buf], tx, ty, acc);
        if (s + 1 < NSTAGE) {
            int nb = buf ^ 1;
            sts_dup(&As[nb][lc + 0][lr * 2], nav.x);
            sts_dup(&As[nb][lc + 1][lr * 2], nav.y);
            sts_dup(&As[nb][lc + 2][lr * 2], nav.z);
            sts_dup(&As[nb][lc + 3][lr * 2], nav.w);
            *(float4*)&Bs[nb][bk][bn] = nbv;
            __syncthreads();
            buf = nb;
        }
    }

    float c[8][8];
    mk_unpack(acc, c);
#pragma unroll
    for (int i = 0; i < 8; i++) {
        long bz = ty * 8 + i;
        float4* cp = (float4*)(g_wc + bz * 65536 + (long)i_dim * 256 + n0 + tx * 8);
        cp[0] = make_float4(c[i][0], c[i][1], c[i][2], c[i][3]);
        cp[1] = make_float4(c[i][4], c[i][5], c[i][6], c[i][7]);
    }
}

// ---------------------------------------------------------------------------
// Kernel B: per bz (blockIdx.z), NN GEMM 256x256x256:
//   C[x][j] = start[b][x][:] @ Wc[bz][:][:]   ->  t[b][x][z][j]
// ---------------------------------------------------------------------------
__global__ __launch_bounds__(256, 2)
void kernB(const float* __restrict__ start)
{
    int bz = blockIdx.z;
    int b = bz >> 4, z = bz & 15;
    const float* A  = start + (long)b * 65536;    // [x][i]
    const float* Bm = g_wc  + (long)bz * 65536;   // [i][j]
    float* C = g_t + (long)b * 1048576 + (long)z * 256;   // +x*4096 +j

    __shared__ float As[2][KT][2 * TILE];
    __shared__ float Bs[2][KT][TILE];

    int tid = threadIdx.x;
    int tx = tid & 15, ty = tid >> 4;
    int m0 = blockIdx.y * TILE;
    int n0 = blockIdx.x * TILE;

    int lr = tid >> 1;
    int lc = (tid & 1) * 4;
    int bk = tid >> 5;
    int bn = (tid & 31) * 4;

    u64 acc[8][4];
#pragma unroll
    for (int i = 0; i < 8; i++)
#pragma unroll
        for (int jp = 0; jp < 4; jp++) acc[i][jp] = 0ULL;

    {
        float4 av = *(const float4*)(A + (long)(m0 + lr) * 256 + lc);
        sts_dup(&As[0][lc + 0][lr * 2], av.x);
        sts_dup(&As[0][lc + 1][lr * 2], av.y);
        sts_dup(&As[0][lc + 2][lr * 2], av.z);
        sts_dup(&As[0][lc + 3][lr * 2], av.w);
        *(float4*)&Bs[0][bk][bn] = *(const float4*)(Bm + (long)bk * 256 + n0 + bn);
    }
    __syncthreads();

    int buf = 0;
#pragma unroll 2
    for (int s = 0; s < NSTAGE; s++) {
        float4 nav, nbv;
        if (s + 1 < NSTAGE) {
            int k1 = (s + 1) * KT;
            nav = *(const float4*)(A + (long)(m0 + lr) * 256 + k1 + lc);
            nbv = *(const float4*)(Bm + (long)(k1 + bk) * 256 + n0 + bn);
        }
        mk_compute(As[buf], Bs[buf], tx, ty, acc);
        if (s + 1 < NSTAGE) {
            int nb = buf ^ 1;
            sts_dup(&As[nb][lc + 0][lr * 2], nav.x);
            sts_dup(&As[nb][lc + 1][lr * 2], nav.y);
            sts_dup(&As[nb][lc + 2][lr * 2], nav.z);
            sts_dup(&As[nb][lc + 3][lr * 2], nav.w);
            *(float4*)&Bs[nb][bk][bn] = nbv;
            __syncthreads();
            buf = nb;
        }
    }

    float c[8][8];
    mk_unpack(acc, c);
#pragma unroll
    for (int i = 0; i < 8; i++) {
        long x = m0 + ty * 8 + i;
        float4* cp = (float4*)(C + x * 4096 + n0 + tx * 8);
        cp[0] = make_float4(c[i][0], c[i][1], c[i][2], c[i][3]);
        cp[1] = make_float4(c[i][4], c[i][5], c[i][6], c[i][7]);
    }
}

// ---------------------------------------------------------------------------
// Kernel C: per b (blockIdx.z), NT GEMM M=4096 (m=x*16+z), N=256 (y), K=256 (j):
//   C[m][y] = t[b][m][:] . end[b][y][:]
// out[b][x][y][z]: addr = b*1048576 + x*4096 + y*16 + z.
// ---------------------------------------------------------------------------
__global__ __launch_bounds__(256, 2)
void kernC(const float* __restrict__ endl, float* __restrict__ out)
{
    int b = blockIdx.z;
    const float* A  = g_t  + (long)b * 1048576;   // [m=4096][j=256]
    const float* Bm = endl + (long)b * 65536;     // [y][j]
    float* O = out + (long)b * 1048576;           // per-b slab 256*256*16

    __shared__ float As[2][KT][2 * TILE];
    __shared__ float Bs[2][KT][TILE];

    int tid = threadIdx.x;
    int tx = tid & 15, ty = tid >> 4;
    int m0 = blockIdx.y * TILE;
    int n0 = blockIdx.x * TILE;

    int lr = tid >> 1;
    int lc = (tid & 1) * 4;

    u64 acc[8][4];
#pragma unroll
    for (int i = 0; i < 8; i++)
#pragma unroll
        for (int jp = 0; jp < 4; jp++) acc[i][jp] = 0ULL;

    {
        float4 av = *(const float4*)(A + (long)(m0 + lr) * 256 + lc);
        sts_dup(&As[0][lc + 0][lr * 2], av.x);
        sts_dup(&As[0][lc + 1][lr * 2], av.y);
        sts_dup(&As[0][lc + 2][lr * 2], av.z);
        sts_dup(&As[0][lc + 3][lr * 2], av.w);
        float4 bv = *(const float4*)(Bm + (long)(n0 + lr) * 256 + lc);
        Bs[0][lc + 0][lr] = bv.x; Bs[0][lc + 1][lr] = bv.y;
        Bs[0][lc + 2][lr] = bv.z; Bs[0][lc + 3][lr] = bv.w;
    }
    __syncthreads();

    int buf = 0;
#pragma unroll 2
    for (int s = 0; s < NSTAGE; s++) {
        float4 nav, nbv;
        if (s + 1 < NSTAGE) {
            int k1 = (s + 1) * KT;
            nav = *(const float4*)(A + (long)(m0 + lr) * 256 + k1 + lc);
            nbv = *(const float4*)(Bm + (long)(n0 + lr) * 256 + k1 + lc);
        }
        mk_compute(As[buf], Bs[buf], tx, ty, acc);
        if (s + 1 < NSTAGE) {
            int nb = buf ^ 1;
            sts_dup(&As[nb][lc + 0][lr * 2], nav.x);
            sts_dup(&As[nb][lc + 1][lr * 2], nav.y);
            sts_dup(&As[nb][lc + 2][lr * 2], nav.z);
            sts_dup(&As[nb][lc + 3][lr * 2], nav.w);
            Bs[nb][lc + 0][lr] = nbv.x; Bs[nb][lc + 1][lr] = nbv.y;
            Bs[nb][lc + 2][lr] = nbv.z; Bs[nb][lc + 3][lr] = nbv.w;
            __syncthreads();
            buf = nb;
        }
    }

    float c[8][8];
    mk_unpack(acc, c);

    // 8 consecutive m = same x, z0 = 0 or 8
    int m = m0 + ty * 8;
    long x  = m >> 4;
    int  z0 = m & 15;
#pragma unroll
    for (int j = 0; j < 8; j++) {
        long y = n0 + tx * 8 + j;
        float* p = O + x * 4096 + y * 16 + z0;
        *(float4*)(p)     = make_float4(c[0][j], c[1][j], c[2][j], c[3][j]);
        *(float4*)(p + 4) = make_float4(c[4][j], c[5][j], c[6][j], c[7][j]);
    }
}

extern "C" void kernel_launch(void* const* d_in, const int* in_sizes, int n_in,
                              void* d_out, int out_size)
{
    const float* start = (const float*)d_in[0];   // [8,256,256]
    const float* endl  = (const float*)d_in[1];   // [8,256,256]
    const float* cls   = (const float*)d_in[2];   // [8,16,256]
    const float* W     = (const float*)d_in[3];   // [256,256,256]
    float* out = (float*)d_out;                   // [8,256,256,16]

    dim3 gA(2, 1, 256);     // j tiles, -, i
    kernA<<<gA, 256>>>(cls, W);

    dim3 gB(2, 2, 128);     // j, x, bz
    kernB<<<gB, 256>>>(start);

    dim3 gC(2, 32, 8);      // y, m(4096/128), b
    kernC<<<gC, 256>>>(endl, out);
}

// round 7
// speedup vs baseline: 1.3650x; 1.3650x over previous
#include <cuda_runtime.h>

// Problem: B=8, L=256, Z=16, H=256
// Reassociated contraction order (12.9 GFLOP total):
//   A: Wc[bz][i][j] = sum_o cls[bz][o] * W[i][o][j]         (per i: GEMM 128x256x256)
//   B: t[b][x][z][j] = sum_i start[b][x][i] * Wc[bz][i][j]  (per bz: GEMM 256x256x256 NN)
//   C: out[b][x][y][z] = sum_j t[b][x][z][j] * end[b][y][j] (per b:  GEMM 4096x256x256 NT)
// FFMA2 inner loop (row-paired accumulators), double-buffered smem,
// conflict-free Bs reads via split-column (tx*4 / 64+tx*4) thread mapping.

__device__ float g_wc[8388608];   // [bz=128][i=256][j=256]
__device__ float g_t [8388608];   // [b=8][x=256][z=16][j=256]

#define TILE 128
#define KT   8
#define NSTAGE 32                 // 256 / KT

typedef unsigned long long u64;

__device__ __forceinline__ u64 dupf(float v) {
    u64 r; unsigned u = __float_as_uint(v);
    asm("mov.b64 %0, {%1, %1};" : "=l"(r) : "r"(u));
    return r;
}
__device__ __forceinline__ void fma2(u64& d, u64 a, u64 b) {
    asm("fma.rn.f32x2 %0, %1, %2, %0;" : "+l"(d) : "l"(a), "l"(b));
}
__device__ __forceinline__ void unpk(u64 v, float& lo, float& hi) {
    unsigned l, h;
    asm("mov.b64 {%0, %1}, %2;" : "=r"(l), "=r"(h) : "l"(v));
    lo = __uint_as_float(l); hi = __uint_as_float(h);
}

// Thread covers rows [ty*8, ty*8+8) and cols {tx*4..tx*4+3} u {64+tx*4..+3}.
// acc[ip][j]: row-pair (ty*8+2ip, +1), j<4 -> col tx*4+j, j>=4 -> col 64+tx*4+j-4.
// Bs read as two float4 at 16B-stride across lanes -> conflict-free.
// As read is intra-phase broadcast -> no bandwidth cost.
__device__ __forceinline__ void mk_compute(const float (*As)[TILE], const float (*Bs)[TILE],
                                           int tx, int ty, u64 acc[4][8])
{
#pragma unroll
    for (int kk = 0; kk < KT; kk++) {
        ulonglong2 a01 = *(const ulonglong2*)&As[kk][ty * 8];
        ulonglong2 a23 = *(const ulonglong2*)&As[kk][ty * 8 + 4];
        u64 ap[4]; ap[0] = a01.x; ap[1] = a01.y; ap[2] = a23.x; ap[3] = a23.y;

        float4 b0 = *(const float4*)&Bs[kk][tx * 4];
        float4 b1 = *(const float4*)&Bs[kk][64 + tx * 4];
        u64 bd[8];
        bd[0] = dupf(b0.x); bd[1] = dupf(b0.y); bd[2] = dupf(b0.z); bd[3] = dupf(b0.w);
        bd[4] = dupf(b1.x); bd[5] = dupf(b1.y); bd[6] = dupf(b1.z); bd[7] = dupf(b1.w);
#pragma unroll
        for (int ip = 0; ip < 4; ip++)
#pragma unroll
            for (int j = 0; j < 8; j++)
                fma2(acc[ip][j], ap[ip], bd[j]);
    }
}

__device__ __forceinline__ void mk_unpack(u64 acc[4][8], float c[8][8])
{
#pragma unroll
    for (int ip = 0; ip < 4; ip++)
#pragma unroll
        for (int j = 0; j < 8; j++)
            unpk(acc[ip][j], c[2 * ip][j], c[2 * ip + 1][j]);
}

// ---------------------------------------------------------------------------
// Kernel A: per i (blockIdx.z), C[bz][j] = cls[bz][:] @ W[i][:][:]
// ---------------------------------------------------------------------------
__global__ __launch_bounds__(256, 2)
void kernA(const float* __restrict__ cls, const float* __restrict__ W)
{
    int i_dim = blockIdx.z;
    const float* A  = cls;                        // [128][256]
    const float* Bm = W + (long)i_dim * 65536;    // [o=256][j=256]

    __shared__ float As[2][KT][TILE];
    __shared__ float Bs[2][KT][TILE];

    int tid = threadIdx.x;
    int tx = tid & 15, ty = tid >> 4;
    int n0 = blockIdx.x * TILE;

    int lr = tid >> 1;          // 0..127
    int lc = (tid & 1) * 4;     // 0 or 4
    int bk = tid >> 5;          // 0..7
    int bn = (tid & 31) * 4;    // 0..124

    u64 acc[4][8];
#pragma unroll
    for (int ip = 0; ip < 4; ip++)
#pragma unroll
        for (int j = 0; j < 8; j++) acc[ip][j] = 0ULL;

    {
        float4 av = *(const float4*)(A + (long)lr * 256 + lc);
        As[0][lc + 0][lr] = av.x; As[0][lc + 1][lr] = av.y;
        As[0][lc + 2][lr] = av.z; As[0][lc + 3][lr] = av.w;
        *(float4*)&Bs[0][bk][bn] = *(const float4*)(Bm + (long)bk * 256 + n0 + bn);
    }
    __syncthreads();

    int buf = 0;
#pragma unroll 2
    for (int s = 0; s < NSTAGE; s++) {
        float4 nav, nbv;
        if (s + 1 < NSTAGE) {
            int k1 = (s + 1) * KT;
            nav = *(const float4*)(A + (long)lr * 256 + k1 + lc);
            nbv = *(const float4*)(Bm + (long)(k1 + bk) * 256 + n0 + bn);
        }
        mk_compute(As[buf], Bs[buf], tx, ty, acc);
        if (s + 1 < NSTAGE) {
            int nb = buf ^ 1;
            As[nb][lc + 0][lr] = nav.x; As[nb][lc + 1][lr] = nav.y;
            As[nb][lc + 2][lr] = nav.z; As[nb][lc + 3][lr] = nav.w;
            *(float4*)&Bs[nb][bk][bn] = nbv;
            __syncthreads();
            buf = nb;
        }
    }

    float c[8][8];
    mk_unpack(acc, c);
#pragma unroll
    for (int i = 0; i < 8; i++) {
        long bz = ty * 8 + i;
        float* base = g_wc + bz * 65536 + (long)i_dim * 256 + n0;
        *(float4*)(base + tx * 4)      = make_float4(c[i][0], c[i][1], c[i][2], c[i][3]);
        *(float4*)(base + 64 + tx * 4) = make_float4(c[i][4], c[i][5], c[i][6], c[i][7]);
    }
}

// ---------------------------------------------------------------------------
// Kernel B: per bz (blockIdx.z), NN GEMM 256x256x256:
//   C[x][j] = start[b][x][:] @ Wc[bz][:][:]   ->  t[b][x][z][j]
// ---------------------------------------------------------------------------
__global__ __launch_bounds__(256, 2)
void kernB(const float* __restrict__ start)
{
    int bz = blockIdx.z;
    int b = bz >> 4, z = bz & 15;
    const float* A  = start + (long)b * 65536;    // [x][i]
    const float* Bm = g_wc  + (long)bz * 65536;   // [i][j]
    float* C = g_t + (long)b * 1048576 + (long)z * 256;   // +x*4096 +j

    __shared__ float As[2][KT][TILE];
    __shared__ float Bs[2][KT][TILE];

    int tid = threadIdx.x;
    int tx = tid & 15, ty = tid >> 4;
    int m0 = blockIdx.y * TILE;
    int n0 = blockIdx.x * TILE;

    int lr = tid >> 1;
    int lc = (tid & 1) * 4;
    int bk = tid >> 5;
    int bn = (tid & 31) * 4;

    u64 acc[4][8];
#pragma unroll
    for (int ip = 0; ip < 4; ip++)
#pragma unroll
        for (int j = 0; j < 8; j++) acc[ip][j] = 0ULL;

    {
        float4 av = *(const float4*)(A + (long)(m0 + lr) * 256 + lc);
        As[0][lc + 0][lr] = av.x; As[0][lc + 1][lr] = av.y;
        As[0][lc + 2][lr] = av.z; As[0][lc + 3][lr] = av.w;
        *(float4*)&Bs[0][bk][bn] = *(const float4*)(Bm + (long)bk * 256 + n0 + bn);
    }
    __syncthreads();

    int buf = 0;
#pragma unroll 2
    for (int s = 0; s < NSTAGE; s++) {
        float4 nav, nbv;
        if (s + 1 < NSTAGE) {
            int k1 = (s + 1) * KT;
            nav = *(const float4*)(A + (long)(m0 + lr) * 256 + k1 + lc);
            nbv = *(const float4*)(Bm + (long)(k1 + bk) * 256 + n0 + bn);
        }
        mk_compute(As[buf], Bs[buf], tx, ty, acc);
        if (s + 1 < NSTAGE) {
            int nb = buf ^ 1;
            As[nb][lc + 0][lr] = nav.x; As[nb][lc + 1][lr] = nav.y;
            As[nb][lc + 2][lr] = nav.z; As[nb][lc + 3][lr] = nav.w;
            *(float4*)&Bs[nb][bk][bn] = nbv;
            __syncthreads();
            buf = nb;
        }
    }

    float c[8][8];
    mk_unpack(acc, c);
#pragma unroll
    for (int i = 0; i < 8; i++) {
        long x = m0 + ty * 8 + i;
        float* base = C + x * 4096 + n0;
        *(float4*)(base + tx * 4)      = make_float4(c[i][0], c[i][1], c[i][2], c[i][3]);
        *(float4*)(base + 64 + tx * 4) = make_float4(c[i][4], c[i][5], c[i][6], c[i][7]);
    }
}

// ---------------------------------------------------------------------------
// Kernel C: per b (blockIdx.z), NT GEMM M=4096 (m=x*16+z), N=256 (y), K=256 (j):
//   C[m][y] = t[b][m][:] . end[b][y][:]
// out[b][x][y][z]: addr = b*1048576 + x*4096 + y*16 + z.
// ---------------------------------------------------------------------------
__global__ __launch_bounds__(256, 2)
void kernC(const float* __restrict__ endl, float* __restrict__ out)
{
    int b = blockIdx.z;
    const float* A  = g_t  + (long)b * 1048576;   // [m=4096][j=256]
    const float* Bm = endl + (long)b * 65536;     // [y][j]
    float* O = out + (long)b * 1048576;           // per-b slab 256*256*16

    __shared__ float As[2][KT][TILE];
    __shared__ float Bs[2][KT][TILE];

    int tid = threadIdx.x;
    int tx = tid & 15, ty = tid >> 4;
    int m0 = blockIdx.y * TILE;
    int n0 = blockIdx.x * TILE;

    int lr = tid >> 1;
    int lc = (tid & 1) * 4;

    u64 acc[4][8];
#pragma unroll
    for (int ip = 0; ip < 4; ip++)
#pragma unroll
        for (int j = 0; j < 8; j++) acc[ip][j] = 0ULL;

    {
        float4 av = *(const float4*)(A + (long)(m0 + lr) * 256 + lc);
        As[0][lc + 0][lr] = av.x; As[0][lc + 1][lr] = av.y;
        As[0][lc + 2][lr] = av.z; As[0][lc + 3][lr] = av.w;
        float4 bv = *(const float4*)(Bm + (long)(n0 + lr) * 256 + lc);
        Bs[0][lc + 0][lr] = bv.x; Bs[0][lc + 1][lr] = bv.y;
        Bs[0][lc + 2][lr] = bv.z; Bs[0][lc + 3][lr] = bv.w;
    }
    __syncthreads();

    int buf = 0;
#pragma unroll 2
    for (int s = 0; s < NSTAGE; s++) {
        float4 nav, nbv;
        if (s + 1 < NSTAGE) {
            int k1 = (s + 1) * KT;
            nav = *(const float4*)(A + (long)(m0 + lr) * 256 + k1 + lc);
            nbv = *(const float4*)(Bm + (long)(n0 + lr) * 256 + k1 + lc);
        }
        mk_compute(As[buf], Bs[buf], tx, ty, acc);
        if (s + 1 < NSTAGE) {
            int nb = buf ^ 1;
            As[nb][lc + 0][lr] = nav.x; As[nb][lc + 1][lr] = nav.y;
            As[nb][lc + 2][lr] = nav.z; As[nb][lc + 3][lr] = nav.w;
            Bs[nb][lc + 0][lr] = nbv.x; Bs[nb][lc + 1][lr] = nbv.y;
            Bs[nb][lc + 2][lr] = nbv.z; Bs[nb][lc + 3][lr] = nbv.w;
            __syncthreads();
            buf = nb;
        }
    }

    float c[8][8];
    mk_unpack(acc, c);

    // rows: 8 consecutive m = same x, z0 = 0 or 8. cols split: tx*4 and 64+tx*4.
    int m = m0 + ty * 8;
    long x  = m >> 4;
    int  z0 = m & 15;
#pragma unroll
    for (int j = 0; j < 8; j++) {
        long y = n0 + (j < 4 ? (tx * 4 + j) : (64 + tx * 4 + j - 4));
        float* p = O + x * 4096 + y * 16 + z0;
        *(float4*)(p)     = make_float4(c[0][j], c[1][j], c[2][j], c[3][j]);
        *(float4*)(p + 4) = make_float4(c[4][j], c[5][j], c[6][j], c[7][j]);
    }
}

extern "C" void kernel_launch(void* const* d_in, const int* in_sizes, int n_in,
                              void* d_out, int out_size)
{
    const float* start = (const float*)d_in[0];   // [8,256,256]
    const float* endl  = (const float*)d_in[1];   // [8,256,256]
    const float* cls   = (const float*)d_in[2];   // [8,16,256]
    const float* W     = (const float*)d_in[3];   // [256,256,256]
    float* out = (float*)d_out;                   // [8,256,256,16]

    dim3 gA(2, 1, 256);     // j tiles, -, i
    kernA<<<gA, 256>>>(cls, W);

    dim3 gB(2, 2, 128);     // j, x, bz
    kernB<<<gB, 256>>>(start);

    dim3 gC(2, 32, 8);      // y, m(4096/128), b
    kernC<<<gC, 256>>>(endl, out);
}